// round 1
// baseline (speedup 1.0000x reference)
#include <cuda_runtime.h>
#include <cuda_bf16.h>
#include <cstdint>

#define KN      100000     // nodes
#define KE      1600000    // edges
#define KIN     256        // in channels
#define KED     64         // edge dim
#define KH      4          // heads
#define KC      32         // channels/head
#define KHC     128        // H*C

#define FULLM 0xFFFFFFFFu

// ---------------- scratch (static device globals; no allocation) ----------------
__device__ float4 g_xproj[KN * 32];        // [N][128] as float4   (51.2 MB)
__device__ float4 g_asrc[KN];              // [N][4]
__device__ float4 g_adst[KN];              // [N][4]
__device__ float  g_W2[KED * KH];          // [64][4]
__device__ float  g_colsum[KED];
__device__ float  g_loopae[KH];
__device__ int    g_deg[KN];
__device__ int    g_off[KN + 1];
__device__ int    g_cursor[KN];
__device__ int    g_ssrc[KE];
__device__ float4 g_salpha[KE];            // [E][4]  (25.6 MB)

// ---------------- reset ----------------
__global__ void k_reset(int n) {
    int i = blockIdx.x * blockDim.x + threadIdx.x;
    if (i < n) g_deg[i] = 0;
    if (i < KED) g_colsum[i] = 0.f;
}

// ---------------- W2[d][h] = sum_c W_edge[d, h*32+c] * att_edge[h, c] ----------------
__global__ void k_w2(const float* __restrict__ W_edge, const float* __restrict__ att_edge) {
    int t = threadIdx.x;                 // 256 threads
    int d = t >> 2, h = t & 3;
    float s = 0.f;
    #pragma unroll 8
    for (int c = 0; c < KC; c++)
        s += W_edge[d * KHC + h * KC + c] * att_edge[h * KC + c];
    g_W2[d * KH + h] = s;
}

// ---------------- GEMM: x_proj = x[N,256] @ W[256,128] ----------------
// 256 threads, tile 64(M) x 128(N), K-chunks of 16, 8x4 per-thread microtile
__global__ __launch_bounds__(256) void k_gemm(const float* __restrict__ x,
                                              const float* __restrict__ W, int n) {
    __shared__ float Xs[16][64];
    __shared__ float Ws[16][128];
    int tid = threadIdx.x;
    int bm = blockIdx.x * 64;
    int row_t = tid >> 5;        // 0..7
    int col_t = tid & 31;        // 0..31
    int row8 = row_t * 8;
    int col4 = col_t * 4;

    float acc[8][4];
    #pragma unroll
    for (int i = 0; i < 8; i++)
        #pragma unroll
        for (int j = 0; j < 4; j++) acc[i][j] = 0.f;

    int lm = tid >> 2;           // 0..63 : m row to load
    int lkq = tid & 3;           // quad within K16

    for (int kb = 0; kb < KIN; kb += 16) {
        // load X tile (transposed into Xs[k][m])
        {
            int gm = bm + lm;
            float4 v = make_float4(0.f, 0.f, 0.f, 0.f);
            if (gm < n) v = *(const float4*)(x + (size_t)gm * KIN + kb + lkq * 4);
            Xs[lkq * 4 + 0][lm] = v.x;
            Xs[lkq * 4 + 1][lm] = v.y;
            Xs[lkq * 4 + 2][lm] = v.z;
            Xs[lkq * 4 + 3][lm] = v.w;
        }
        // load W tile
        #pragma unroll
        for (int jj = 0; jj < 2; jj++) {
            int idx = tid + jj * 256;
            int k = idx >> 5;
            int c = (idx & 31) * 4;
            *(float4*)&Ws[k][c] = *(const float4*)(W + (size_t)(kb + k) * KHC + c);
        }
        __syncthreads();
        #pragma unroll
        for (int k = 0; k < 16; k++) {
            float4 a0 = *(const float4*)&Xs[k][row8];
            float4 a1 = *(const float4*)&Xs[k][row8 + 4];
            float4 b  = *(const float4*)&Ws[k][col4];
            float av[8] = {a0.x, a0.y, a0.z, a0.w, a1.x, a1.y, a1.z, a1.w};
            #pragma unroll
            for (int i = 0; i < 8; i++) {
                acc[i][0] += av[i] * b.x;
                acc[i][1] += av[i] * b.y;
                acc[i][2] += av[i] * b.z;
                acc[i][3] += av[i] * b.w;
            }
        }
        __syncthreads();
    }
    #pragma unroll
    for (int i = 0; i < 8; i++) {
        int gm = bm + row8 + i;
        if (gm < n)
            g_xproj[(size_t)gm * 32 + col_t] =
                make_float4(acc[i][0], acc[i][1], acc[i][2], acc[i][3]);
    }
}

// ---------------- a_src / a_dst: warp per node ----------------
__global__ void k_attn(const float* __restrict__ att_src,
                       const float* __restrict__ att_dst, int n) {
    int warp = (blockIdx.x * blockDim.x + threadIdx.x) >> 5;
    int lane = threadIdx.x & 31;
    if (warp >= n) return;
    float4 xp = g_xproj[(size_t)warp * 32 + lane];
    float4 as = *(const float4*)(att_src + lane * 4);
    float4 ad = *(const float4*)(att_dst + lane * 4);
    float ds = xp.x * as.x + xp.y * as.y + xp.z * as.z + xp.w * as.w;
    float dd = xp.x * ad.x + xp.y * ad.y + xp.z * ad.z + xp.w * ad.w;
    #pragma unroll
    for (int m = 1; m <= 4; m <<= 1) {
        ds += __shfl_xor_sync(FULLM, ds, m);
        dd += __shfl_xor_sync(FULLM, dd, m);
    }
    if ((lane & 7) == 0) {
        int h = lane >> 3;
        ((float*)&g_asrc[warp])[h] = ds;
        ((float*)&g_adst[warp])[h] = dd;
    }
}

// ---------------- histogram of dst ----------------
__global__ void k_hist(const int* __restrict__ edge_index, int E) {
    int e = blockIdx.x * blockDim.x + threadIdx.x;
    if (e < E) atomicAdd(&g_deg[edge_index[E + e]], 1);
}

// ---------------- single-block scan ----------------
__global__ void k_scan(int n) {
    __shared__ int s[1024];
    int t = threadIdx.x;
    int chunk = (n + 1023) / 1024;
    int start = t * chunk;
    int sum = 0;
    for (int j = 0; j < chunk; j++) {
        int i = start + j;
        if (i < n) sum += g_deg[i];
    }
    s[t] = sum;
    __syncthreads();
    for (int o = 1; o < 1024; o <<= 1) {
        int v = (t >= o) ? s[t - o] : 0;
        __syncthreads();
        s[t] += v;
        __syncthreads();
    }
    int run = s[t] - sum;
    for (int j = 0; j < chunk; j++) {
        int i = start + j;
        if (i < n) {
            g_off[i] = run;
            g_cursor[i] = run;
            run += g_deg[i];
        }
    }
    if (t == 1023) g_off[n] = s[1023];
}

// ---------------- scatter: warp per edge; fuses a_edge matvec + colsum + CSR build ----------------
__global__ __launch_bounds__(256) void k_scatter(const int* __restrict__ edge_index,
                                                 const float* __restrict__ edge_attr, int E) {
    __shared__ float Ws2[KED * KH];
    __shared__ float cs[KED];
    int tid = threadIdx.x;
    if (tid < KED * KH) Ws2[tid] = g_W2[tid];
    if (tid < KED) cs[tid] = 0.f;
    __syncthreads();

    int e = (blockIdx.x * blockDim.x + tid) >> 5;
    int lane = tid & 31;
    if (e < E) {
        float ea0 = edge_attr[(size_t)e * KED + lane];
        float ea1 = edge_attr[(size_t)e * KED + 32 + lane];
        atomicAdd(&cs[lane], ea0);
        atomicAdd(&cs[lane + 32], ea1);
        float p0 = ea0 * Ws2[lane * 4 + 0] + ea1 * Ws2[(lane + 32) * 4 + 0];
        float p1 = ea0 * Ws2[lane * 4 + 1] + ea1 * Ws2[(lane + 32) * 4 + 1];
        float p2 = ea0 * Ws2[lane * 4 + 2] + ea1 * Ws2[(lane + 32) * 4 + 2];
        float p3 = ea0 * Ws2[lane * 4 + 3] + ea1 * Ws2[(lane + 32) * 4 + 3];
        #pragma unroll
        for (int m = 16; m >= 1; m >>= 1) {
            p0 += __shfl_xor_sync(FULLM, p0, m);
            p1 += __shfl_xor_sync(FULLM, p1, m);
            p2 += __shfl_xor_sync(FULLM, p2, m);
            p3 += __shfl_xor_sync(FULLM, p3, m);
        }
        if (lane == 0) {
            int src = edge_index[e];
            int dst = edge_index[E + e];
            float4 as = g_asrc[src];
            int pos = atomicAdd(&g_cursor[dst], 1);
            g_ssrc[pos] = src;
            g_salpha[pos] = make_float4(as.x + p0, as.y + p1, as.z + p2, as.w + p3);
        }
    }
    __syncthreads();
    if (tid < KED) atomicAdd(&g_colsum[tid], cs[tid]);
}

// ---------------- loop a_edge = (colmean) @ W2 ----------------
__global__ void k_loopae(int E) {
    int h = threadIdx.x;
    if (h >= KH) return;
    float invE = 1.0f / (float)E;
    float s = 0.f;
    for (int d = 0; d < KED; d++) s += g_colsum[d] * g_W2[d * 4 + h];
    g_loopae[h] = s * invE;
}

// ---------------- aggregation: warp per node, fused softmax + weighted sum ----------------
__global__ __launch_bounds__(256) void k_agg(const float* __restrict__ bias,
                                             float* __restrict__ out, int n) {
    int i = (blockIdx.x * blockDim.x + threadIdx.x) >> 5;
    int lane = threadIdx.x & 31;
    if (i >= n) return;

    int hl = lane >> 3;     // head for accumulation lanes
    int sub = lane & 3;     // head for exp lanes

    float adst_s = ((const float*)&g_adst[i])[sub];
    float asrc_s = ((const float*)&g_asrc[i])[sub];
    float lae_s  = g_loopae[sub];
    float4 xpi = g_xproj[(size_t)i * 32 + lane];

    float4 acc = make_float4(0.f, 0.f, 0.f, 0.f);
    float dsum = 0.f;

    // self loop
    float vs = asrc_s + adst_s + lae_s;
    vs = vs > 0.f ? vs : 0.2f * vs;
    float ws = __expf(vs);
    if (lane < 4) dsum += ws;
    {
        float w = __shfl_sync(FULLM, ws, hl);
        acc.x += w * xpi.x; acc.y += w * xpi.y; acc.z += w * xpi.z; acc.w += w * xpi.w;
    }

    int beg = g_off[i], end = g_off[i + 1];
    const float* salpha_f = (const float*)g_salpha;
    for (int base = beg; base < end; base += 8) {
        int myedge = base + (lane >> 2);
        float w = 0.f;
        if (myedge < end) {
            float a = salpha_f[(size_t)base * 4 + lane] + adst_s;
            a = a > 0.f ? a : 0.2f * a;
            w = __expf(a);
        }
        dsum += w;
        int sv = 0;
        if (lane < 8 && base + lane < end) sv = g_ssrc[base + lane];
        int lim = end - base; if (lim > 8) lim = 8;
        #pragma unroll
        for (int k = 0; k < 8; k++) {
            if (k >= lim) break;
            int s = __shfl_sync(FULLM, sv, k);
            float we = __shfl_sync(FULLM, w, k * 4 + hl);
            float4 xp = g_xproj[(size_t)s * 32 + lane];
            acc.x += we * xp.x; acc.y += we * xp.y;
            acc.z += we * xp.z; acc.w += we * xp.w;
        }
    }
    // reduce dsum across the 8 lanes sharing (lane&3)
    #pragma unroll
    for (int m = 4; m <= 16; m <<= 1) dsum += __shfl_xor_sync(FULLM, dsum, m);
    float denom = __shfl_sync(FULLM, dsum, hl);
    float inv = 1.0f / denom;
    float4 b4 = *(const float4*)(bias + lane * 4);
    float4 o;
    o.x = acc.x * inv + b4.x;
    o.y = acc.y * inv + b4.y;
    o.z = acc.z * inv + b4.z;
    o.w = acc.w * inv + b4.w;
    *(float4*)(out + (size_t)i * KHC + lane * 4) = o;
}

// ---------------- launch ----------------
extern "C" void kernel_launch(void* const* d_in, const int* in_sizes, int n_in,
                              void* d_out, int out_size) {
    const float* x         = (const float*)d_in[0];
    const int*   edge_idx  = (const int*)d_in[1];
    const float* edge_attr = (const float*)d_in[2];
    const float* W         = (const float*)d_in[3];
    const float* att_src   = (const float*)d_in[4];
    const float* att_dst   = (const float*)d_in[5];
    const float* W_edge    = (const float*)d_in[6];
    const float* att_edge  = (const float*)d_in[7];
    const float* bias      = (const float*)d_in[8];
    float* out = (float*)d_out;

    int n = in_sizes[0] / KIN;       // 100000
    int E = in_sizes[1] / 2;         // 1600000

    k_reset<<<(n + 255) / 256, 256>>>(n);
    k_w2<<<1, 256>>>(W_edge, att_edge);
    k_gemm<<<(n + 63) / 64, 256>>>(x, W, n);
    k_attn<<<(n + 7) / 8, 256>>>(att_src, att_dst, n);
    k_hist<<<(E + 255) / 256, 256>>>(edge_idx, E);
    k_scan<<<1, 1024>>>(n);
    k_scatter<<<(E + 7) / 8, 256>>>(edge_idx, edge_attr, E);
    k_loopae<<<1, 32>>>(E);
    k_agg<<<(n + 7) / 8, 256>>>(bias, out, n);
}

// round 2
// speedup vs baseline: 1.5612x; 1.5612x over previous
#include <cuda_runtime.h>
#include <cuda_bf16.h>
#include <cstdint>

#define KN      100000     // nodes
#define KE      1600000    // edges
#define KIN     256        // in channels
#define KED     64         // edge dim
#define KH      4          // heads
#define KC      32         // channels/head
#define KHC     128        // H*C
#define KNB     ((KE + 7) / 8)   // scatter blocks

#define FULLM 0xFFFFFFFFu

// ---------------- scratch (static device globals; no allocation) ----------------
__device__ float4 g_xproj[KN * 32];        // [N][128] as float4   (51.2 MB)
__device__ float4 g_asrc[KN];              // [N][4]
__device__ float4 g_adst[KN];              // [N][4]
__device__ float  g_W2[KED * KH];          // [64][4]
__device__ float  g_loopsum[KH];
__device__ float  g_loopae[KH];
__device__ int    g_deg[KN];
__device__ int    g_off[KN + 1];
__device__ int    g_cursor[KN];
__device__ int    g_ssrc[KE];
__device__ float4 g_salpha[KE];            // [E][4]  (25.6 MB)
__device__ float4 g_part[KNB];             // per-block p-sums (3.2 MB)

// ---------------- reset ----------------
__global__ void k_reset(int n) {
    int i = blockIdx.x * blockDim.x + threadIdx.x;
    if (i < n) g_deg[i] = 0;
    if (i < KH) g_loopsum[i] = 0.f;
}

// ---------------- W2[d][h] = sum_c W_edge[d, h*32+c] * att_edge[h, c] ----------------
__global__ void k_w2(const float* __restrict__ W_edge, const float* __restrict__ att_edge) {
    int t = threadIdx.x;                 // 256 threads
    int d = t >> 2, h = t & 3;
    float s = 0.f;
    #pragma unroll 8
    for (int c = 0; c < KC; c++)
        s += W_edge[d * KHC + h * KC + c] * att_edge[h * KC + c];
    g_W2[d * KH + h] = s;
}

// ---------------- GEMM: x_proj = x[N,256] @ W[256,128] ----------------
// 256 threads, tile 128(M) x 128(N), K-chunks of 16, 8x8 per-thread microtile.
// Per-thread cols: {tx*4 .. tx*4+3} and {64+tx*4 .. 64+tx*4+3} (conflict-free LDS).
__global__ __launch_bounds__(256) void k_gemm(const float* __restrict__ x,
                                              const float* __restrict__ W, int n) {
    __shared__ float Xs[16][128];
    __shared__ float Ws[16][128];
    int tid = threadIdx.x;
    int bm = blockIdx.x * 128;
    int tx = tid & 15;           // 0..15
    int ty = tid >> 4;           // 0..15

    float acc[8][8];
    #pragma unroll
    for (int i = 0; i < 8; i++)
        #pragma unroll
        for (int j = 0; j < 8; j++) acc[i][j] = 0.f;

    int xr = tid >> 2;           // 0..63
    int xk = (tid & 3) << 2;     // 0,4,8,12
    int wk = tid >> 5;           // 0..7
    int wn = (tid & 31) << 2;    // 0..124

    for (int kb = 0; kb < KIN; kb += 16) {
        // X tile: 128 rows x 16 k, transposed into Xs[k][m]; two half-passes
        #pragma unroll
        for (int h = 0; h < 2; h++) {
            int m = xr + h * 64;
            int gm = bm + m;
            float4 v = make_float4(0.f, 0.f, 0.f, 0.f);
            if (gm < n) v = *(const float4*)(x + (size_t)gm * KIN + kb + xk);
            Xs[xk + 0][m] = v.x;
            Xs[xk + 1][m] = v.y;
            Xs[xk + 2][m] = v.z;
            Xs[xk + 3][m] = v.w;
        }
        // W tile: 16 rows x 128 cols, two passes of 8 rows
        #pragma unroll
        for (int h = 0; h < 2; h++) {
            int k = wk + h * 8;
            *(float4*)&Ws[k][wn] = *(const float4*)(W + (size_t)(kb + k) * KHC + wn);
        }
        __syncthreads();
        #pragma unroll
        for (int k = 0; k < 16; k++) {
            float4 a0 = *(const float4*)&Xs[k][ty * 8];
            float4 a1 = *(const float4*)&Xs[k][ty * 8 + 4];
            float4 b0 = *(const float4*)&Ws[k][tx * 4];
            float4 b1 = *(const float4*)&Ws[k][tx * 4 + 64];
            float av[8] = {a0.x, a0.y, a0.z, a0.w, a1.x, a1.y, a1.z, a1.w};
            float bv[8] = {b0.x, b0.y, b0.z, b0.w, b1.x, b1.y, b1.z, b1.w};
            #pragma unroll
            for (int i = 0; i < 8; i++)
                #pragma unroll
                for (int j = 0; j < 8; j++)
                    acc[i][j] += av[i] * bv[j];
        }
        __syncthreads();
    }
    #pragma unroll
    for (int i = 0; i < 8; i++) {
        int gm = bm + ty * 8 + i;
        if (gm < n) {
            g_xproj[(size_t)gm * 32 + tx] =
                make_float4(acc[i][0], acc[i][1], acc[i][2], acc[i][3]);
            g_xproj[(size_t)gm * 32 + 16 + tx] =
                make_float4(acc[i][4], acc[i][5], acc[i][6], acc[i][7]);
        }
    }
}

// ---------------- a_src / a_dst: warp per node ----------------
__global__ void k_attn(const float* __restrict__ att_src,
                       const float* __restrict__ att_dst, int n) {
    int warp = (blockIdx.x * blockDim.x + threadIdx.x) >> 5;
    int lane = threadIdx.x & 31;
    if (warp >= n) return;
    float4 xp = g_xproj[(size_t)warp * 32 + lane];
    float4 as = *(const float4*)(att_src + lane * 4);
    float4 ad = *(const float4*)(att_dst + lane * 4);
    float ds = xp.x * as.x + xp.y * as.y + xp.z * as.z + xp.w * as.w;
    float dd = xp.x * ad.x + xp.y * ad.y + xp.z * ad.z + xp.w * ad.w;
    #pragma unroll
    for (int m = 1; m <= 4; m <<= 1) {
        ds += __shfl_xor_sync(FULLM, ds, m);
        dd += __shfl_xor_sync(FULLM, dd, m);
    }
    if ((lane & 7) == 0) {
        int h = lane >> 3;
        ((float*)&g_asrc[warp])[h] = ds;
        ((float*)&g_adst[warp])[h] = dd;
    }
}

// ---------------- histogram of dst ----------------
__global__ void k_hist(const int* __restrict__ edge_index, int E) {
    int e = blockIdx.x * blockDim.x + threadIdx.x;
    if (e < E) atomicAdd(&g_deg[edge_index[E + e]], 1);
}

// ---------------- single-block scan ----------------
__global__ void k_scan(int n) {
    __shared__ int s[1024];
    int t = threadIdx.x;
    int chunk = (n + 1023) / 1024;
    int start = t * chunk;
    int sum = 0;
    for (int j = 0; j < chunk; j++) {
        int i = start + j;
        if (i < n) sum += g_deg[i];
    }
    s[t] = sum;
    __syncthreads();
    for (int o = 1; o < 1024; o <<= 1) {
        int v = (t >= o) ? s[t - o] : 0;
        __syncthreads();
        s[t] += v;
        __syncthreads();
    }
    int run = s[t] - sum;
    for (int j = 0; j < chunk; j++) {
        int i = start + j;
        if (i < n) {
            g_off[i] = run;
            g_cursor[i] = run;
            run += g_deg[i];
        }
    }
    if (t == 1023) g_off[n] = s[1023];
}

// ---------------- scatter: warp per edge; a_edge matvec + CSR build ----------------
// p-sums reduced per block into g_part (NON-atomic global writes), final reduce in k_psum.
__global__ __launch_bounds__(256) void k_scatter(const int* __restrict__ edge_index,
                                                 const float* __restrict__ edge_attr, int E) {
    __shared__ float Ws2[KED * KH];
    __shared__ float bp[KH];
    int tid = threadIdx.x;
    Ws2[tid] = g_W2[tid];
    if (tid < KH) bp[tid] = 0.f;
    __syncthreads();

    int e = (blockIdx.x * blockDim.x + tid) >> 5;
    int lane = tid & 31;
    if (e < E) {
        float ea0 = edge_attr[(size_t)e * KED + lane];
        float ea1 = edge_attr[(size_t)e * KED + 32 + lane];
        float p0 = ea0 * Ws2[lane * 4 + 0] + ea1 * Ws2[(lane + 32) * 4 + 0];
        float p1 = ea0 * Ws2[lane * 4 + 1] + ea1 * Ws2[(lane + 32) * 4 + 1];
        float p2 = ea0 * Ws2[lane * 4 + 2] + ea1 * Ws2[(lane + 32) * 4 + 2];
        float p3 = ea0 * Ws2[lane * 4 + 3] + ea1 * Ws2[(lane + 32) * 4 + 3];
        #pragma unroll
        for (int m = 16; m >= 1; m >>= 1) {
            p0 += __shfl_xor_sync(FULLM, p0, m);
            p1 += __shfl_xor_sync(FULLM, p1, m);
            p2 += __shfl_xor_sync(FULLM, p2, m);
            p3 += __shfl_xor_sync(FULLM, p3, m);
        }
        if (lane == 0) {
            atomicAdd(&bp[0], p0);
            atomicAdd(&bp[1], p1);
            atomicAdd(&bp[2], p2);
            atomicAdd(&bp[3], p3);
            int src = edge_index[e];
            int dst = edge_index[E + e];
            float4 as = g_asrc[src];
            int pos = atomicAdd(&g_cursor[dst], 1);
            g_ssrc[pos] = src;
            g_salpha[pos] = make_float4(as.x + p0, as.y + p1, as.z + p2, as.w + p3);
        }
    }
    __syncthreads();
    if (tid < KH) ((float*)&g_part[blockIdx.x])[tid] = bp[tid];
}

// ---------------- reduce per-block p-sums ----------------
__global__ void k_psum(int nb) {
    int tid = blockIdx.x * blockDim.x + threadIdx.x;
    int stride = gridDim.x * blockDim.x;
    float4 s = make_float4(0.f, 0.f, 0.f, 0.f);
    for (int j = tid; j < nb; j += stride) {
        float4 v = g_part[j];
        s.x += v.x; s.y += v.y; s.z += v.z; s.w += v.w;
    }
    #pragma unroll
    for (int m = 16; m >= 1; m >>= 1) {
        s.x += __shfl_xor_sync(FULLM, s.x, m);
        s.y += __shfl_xor_sync(FULLM, s.y, m);
        s.z += __shfl_xor_sync(FULLM, s.z, m);
        s.w += __shfl_xor_sync(FULLM, s.w, m);
    }
    __shared__ float4 ws[8];
    int warp = threadIdx.x >> 5;
    int lane = threadIdx.x & 31;
    if (lane == 0) ws[warp] = s;
    __syncthreads();
    if (warp == 0) {
        float4 v = (lane < 8) ? ws[lane] : make_float4(0.f, 0.f, 0.f, 0.f);
        #pragma unroll
        for (int m = 4; m >= 1; m >>= 1) {
            v.x += __shfl_xor_sync(FULLM, v.x, m);
            v.y += __shfl_xor_sync(FULLM, v.y, m);
            v.z += __shfl_xor_sync(FULLM, v.z, m);
            v.w += __shfl_xor_sync(FULLM, v.w, m);
        }
        if (lane == 0) {
            atomicAdd(&g_loopsum[0], v.x);
            atomicAdd(&g_loopsum[1], v.y);
            atomicAdd(&g_loopsum[2], v.z);
            atomicAdd(&g_loopsum[3], v.w);
        }
    }
}

// ---------------- loop a_edge = psum / E ----------------
__global__ void k_loopae(int E) {
    int h = threadIdx.x;
    if (h < KH) g_loopae[h] = g_loopsum[h] / (float)E;
}

// ---------------- aggregation: warp per node, fused softmax + weighted sum ----------------
__global__ __launch_bounds__(256) void k_agg(const float* __restrict__ bias,
                                             float* __restrict__ out, int n) {
    int i = (blockIdx.x * blockDim.x + threadIdx.x) >> 5;
    int lane = threadIdx.x & 31;
    if (i >= n) return;

    int hl = lane >> 3;     // head for accumulation lanes
    int sub = lane & 3;     // head for exp lanes

    float adst_s = ((const float*)&g_adst[i])[sub];
    float asrc_s = ((const float*)&g_asrc[i])[sub];
    float lae_s  = g_loopae[sub];
    float4 xpi = g_xproj[(size_t)i * 32 + lane];

    float4 acc = make_float4(0.f, 0.f, 0.f, 0.f);
    float dsum = 0.f;

    // self loop
    float vs = asrc_s + adst_s + lae_s;
    vs = vs > 0.f ? vs : 0.2f * vs;
    float ws = __expf(vs);
    if (lane < 4) dsum += ws;
    {
        float w = __shfl_sync(FULLM, ws, hl);
        acc.x += w * xpi.x; acc.y += w * xpi.y; acc.z += w * xpi.z; acc.w += w * xpi.w;
    }

    int beg = g_off[i], end = g_off[i + 1];
    const float* salpha_f = (const float*)g_salpha;
    for (int base = beg; base < end; base += 8) {
        int myedge = base + (lane >> 2);
        float w = 0.f;
        if (myedge < end) {
            float a = salpha_f[(size_t)base * 4 + lane] + adst_s;
            a = a > 0.f ? a : 0.2f * a;
            w = __expf(a);
        }
        dsum += w;
        // clamp out-of-range sources to self row (weight is 0 there) -> branch-free gathers
        int sv = i;
        if (lane < 8 && base + lane < end) sv = g_ssrc[base + lane];
        #pragma unroll
        for (int k = 0; k < 8; k++) {
            int s = __shfl_sync(FULLM, sv, k);
            float we = __shfl_sync(FULLM, w, k * 4 + hl);
            float4 xp = g_xproj[(size_t)s * 32 + lane];
            acc.x += we * xp.x; acc.y += we * xp.y;
            acc.z += we * xp.z; acc.w += we * xp.w;
        }
    }
    // reduce dsum across the 8 lanes sharing (lane&3)
    #pragma unroll
    for (int m = 4; m <= 16; m <<= 1) dsum += __shfl_xor_sync(FULLM, dsum, m);
    float denom = __shfl_sync(FULLM, dsum, hl);
    float inv = 1.0f / denom;
    float4 b4 = *(const float4*)(bias + lane * 4);
    float4 o;
    o.x = acc.x * inv + b4.x;
    o.y = acc.y * inv + b4.y;
    o.z = acc.z * inv + b4.z;
    o.w = acc.w * inv + b4.w;
    *(float4*)(out + (size_t)i * KHC + lane * 4) = o;
}

// ---------------- launch ----------------
extern "C" void kernel_launch(void* const* d_in, const int* in_sizes, int n_in,
                              void* d_out, int out_size) {
    const float* x         = (const float*)d_in[0];
    const int*   edge_idx  = (const int*)d_in[1];
    const float* edge_attr = (const float*)d_in[2];
    const float* W         = (const float*)d_in[3];
    const float* att_src   = (const float*)d_in[4];
    const float* att_dst   = (const float*)d_in[5];
    const float* W_edge    = (const float*)d_in[6];
    const float* att_edge  = (const float*)d_in[7];
    const float* bias      = (const float*)d_in[8];
    float* out = (float*)d_out;

    int n = in_sizes[0] / KIN;       // 100000
    int E = in_sizes[1] / 2;         // 1600000
    int nb = (E + 7) / 8;            // scatter blocks

    k_reset<<<(n + 255) / 256, 256>>>(n);
    k_w2<<<1, 256>>>(W_edge, att_edge);
    k_gemm<<<(n + 127) / 128, 256>>>(x, W, n);
    k_attn<<<(n + 7) / 8, 256>>>(att_src, att_dst, n);
    k_hist<<<(E + 255) / 256, 256>>>(edge_idx, E);
    k_scan<<<1, 1024>>>(n);
    k_scatter<<<nb, 256>>>(edge_idx, edge_attr, E);
    k_psum<<<64, 256>>>(nb);
    k_loopae<<<1, 32>>>(E);
    k_agg<<<(n + 7) / 8, 256>>>(bias, out, n);
}